// round 8
// baseline (speedup 1.0000x reference)
#include <cuda_runtime.h>
#include <cuda_bf16.h>
#include <cstdint>

#define HH 512
#define WW 512
#define BATCH 32
#define THREADS 128
#define OUTW 256          // output cols per tile (2 per thread)
#define OUTH 8            // output rows per tile
#define SPITCH 264        // smem row pitch (floats): 4 left halo + 256 + 4 right
#define TILE_H (OUTH + 6) // 14
#define NCH 66            // 16-byte chunks per row per map (264 floats / 4)

typedef unsigned long long u64;

__device__ double g_acc = 0.0;
__device__ unsigned int g_tick = 0;

// ---- packed f32x2 helpers ----
static __device__ __forceinline__ u64 fma2_(u64 a, u64 b, u64 c) {
    u64 d; asm("fma.rn.f32x2 %0,%1,%2,%3;" : "=l"(d) : "l"(a), "l"(b), "l"(c)); return d;
}
static __device__ __forceinline__ u64 mul2_(u64 a, u64 b) {
    u64 d; asm("mul.rn.f32x2 %0,%1,%2;" : "=l"(d) : "l"(a), "l"(b)); return d;
}
static __device__ __forceinline__ u64 add2_(u64 a, u64 b) {
    u64 d; asm("add.rn.f32x2 %0,%1,%2;" : "=l"(d) : "l"(a), "l"(b)); return d;
}
static __device__ __forceinline__ u64 pk2(float lo, float hi) {
    u64 r; asm("mov.b64 %0,{%1,%2};" : "=l"(r) : "f"(lo), "f"(hi)); return r;
}
static __device__ __forceinline__ void upk2(u64 v, float& lo, float& hi) {
    asm("mov.b64 {%0,%1},%2;" : "=f"(lo), "=f"(hi) : "l"(v));
}
static __device__ __forceinline__ u64 neg2_(u64 a) { return a ^ 0x8000000080000000ULL; }
// pair {hi(a), lo(b)} — register re-pairing only (no shifts)
static __device__ __forceinline__ u64 sh2_(u64 a, u64 b) {
    unsigned al, ah, bl, bh;
    asm("mov.b64 {%0,%1},%2;" : "=r"(al), "=r"(ah) : "l"(a));
    asm("mov.b64 {%0,%1},%2;" : "=r"(bl), "=r"(bh) : "l"(b));
    u64 r;
    asm("mov.b64 %0,{%1,%2};" : "=l"(r) : "r"(ah), "r"(bl));
    return r;
}

static __device__ __forceinline__ void cp16(unsigned saddr, const float* gaddr, int srcsz) {
    asm volatile("cp.async.cg.shared.global [%0], [%1], 16, %2;"
                 :: "r"(saddr), "l"(gaddr), "r"(srcsz));
}

__global__ __launch_bounds__(THREADS, 5) void ssim_main(const float* __restrict__ x,
                                                        const float* __restrict__ y,
                                                        const float* __restrict__ kern,
                                                        float* __restrict__ out,
                                                        int nblocks)
{
    extern __shared__ float smem_dyn[];
    float (*sx)[SPITCH] = (float (*)[SPITCH])smem_dyn;
    float (*sy)[SPITCH] = (float (*)[SPITCH])(smem_dyn + TILE_H * SPITCH);
    __shared__ float wsum[4];

    const int tid  = threadIdx.x;
    const int col0 = blockIdx.x * OUTW;
    const int row0 = blockIdx.y * OUTH;
    const long base = (long)blockIdx.z * (HH * WW);

    // separable 1-D weights: v_i = sqrt(k[i][i])
    u64 w2[7];
#pragma unroll
    for (int t = 0; t < 7; t++) {
        float wt = sqrtf(__ldg(kern + t * 7 + t));
        w2[t] = pk2(wt, wt);
    }

    // ---- stage x,y tile via cp.async 16B chunks (zfill out-of-range) ----
    // smem col s <-> global col (col0 - 4 + s); row r <-> global row (row0 - 3 + r).
    // Each item = one (row, chunk) position; thread copies BOTH x and y chunks.
    // Since col0 in {0,256}, each chunk is fully in-image or fully out (clean zfill).
    for (int i = tid; i < TILE_H * NCH; i += THREADS) {
        int r  = i / NCH;
        int j  = i - r * NCH;
        int gr = row0 - 3 + r;
        int gc = col0 - 4 + 4 * j;
        bool ok = (gr >= 0) && (gr < HH) && (gc >= 0) && (gc < WW);
        long gi = base + (long)gr * WW + gc;
        const float* srcx = ok ? (x + gi) : x;
        const float* srcy = ok ? (y + gi) : y;
        int sz = ok ? 16 : 0;
        cp16((unsigned)__cvta_generic_to_shared(sx[r] + 4 * j), srcx, sz);
        cp16((unsigned)__cvta_generic_to_shared(sy[r] + 4 * j), srcy, sz);
    }
    asm volatile("cp.async.commit_group;");
    asm volatile("cp.async.wait_group 0;");
    __syncthreads();

    const u64 two2 = pk2(2.f, 2.f);
    const u64 c1_2 = pk2(1e-4f, 1e-4f);
    const u64 c2_2 = pk2(9e-4f, 9e-4f);

    u64 Wx[7], Wy[7], Wxx[7], Wyy[7], Wxy[7];
    float sum = 0.f;

    // horizontal 7-tap conv of (x,y,xx,yy,xy); outputs packed pair for global
    // cols (col0+2tid, col0+2tid+1). Aligned LDS.64 at smem cols 2tid..2tid+9;
    // tap t (lo pixel) lives at smem col 2tid+1+t.
#define HCONV(r, s)                                                          \
    {                                                                        \
        const float* rx_ = &sx[(r)][2 * tid];                                \
        const float* ry_ = &sy[(r)][2 * tid];                                \
        u64 e0 = *(const u64*)(rx_ + 0), e1 = *(const u64*)(rx_ + 2);        \
        u64 e2 = *(const u64*)(rx_ + 4), e3 = *(const u64*)(rx_ + 6);        \
        u64 e4 = *(const u64*)(rx_ + 8);                                     \
        u64 f0 = *(const u64*)(ry_ + 0), f1 = *(const u64*)(ry_ + 2);        \
        u64 f2 = *(const u64*)(ry_ + 4), f3 = *(const u64*)(ry_ + 6);        \
        u64 f4 = *(const u64*)(ry_ + 8);                                     \
        u64 xp[7] = {sh2_(e0, e1), e1, sh2_(e1, e2), e2,                     \
                     sh2_(e2, e3), e3, sh2_(e3, e4)};                        \
        u64 yp[7] = {sh2_(f0, f1), f1, sh2_(f1, f2), f2,                     \
                     sh2_(f2, f3), f3, sh2_(f3, f4)};                        \
        u64 wx0 = mul2_(w2[0], xp[0]);                                       \
        u64 wy0 = mul2_(w2[0], yp[0]);                                       \
        u64 a_ = wx0, b_ = wy0;                                              \
        u64 cxx_ = mul2_(wx0, xp[0]);                                        \
        u64 cyy_ = mul2_(wy0, yp[0]);                                        \
        u64 cxy_ = mul2_(wx0, yp[0]);                                        \
        _Pragma("unroll")                                                    \
        for (int t = 1; t < 7; t++) {                                        \
            u64 wx = mul2_(w2[t], xp[t]);                                    \
            u64 wy = mul2_(w2[t], yp[t]);                                    \
            a_   = add2_(a_, wx);                                            \
            b_   = add2_(b_, wy);                                            \
            cxx_ = fma2_(wx, xp[t], cxx_);                                   \
            cyy_ = fma2_(wy, yp[t], cyy_);                                   \
            cxy_ = fma2_(wx, yp[t], cxy_);                                   \
        }                                                                    \
        Wx[(s)] = a_; Wy[(s)] = b_;                                          \
        Wxx[(s)] = cxx_; Wyy[(s)] = cyy_; Wxy[(s)] = cxy_;                   \
    }

#pragma unroll
    for (int r = 0; r < 6; r++) {
        HCONV(r, r);
    }

#pragma unroll
    for (int r = 6; r < TILE_H; r++) {
        HCONV(r, r % 7);

        u64 mx  = mul2_(w2[0], Wx[(r - 6) % 7]);
        u64 my  = mul2_(w2[0], Wy[(r - 6) % 7]);
        u64 exx = mul2_(w2[0], Wxx[(r - 6) % 7]);
        u64 eyy = mul2_(w2[0], Wyy[(r - 6) % 7]);
        u64 exy = mul2_(w2[0], Wxy[(r - 6) % 7]);
#pragma unroll
        for (int t = 1; t < 7; t++) {
            int s = (r - 6 + t) % 7;
            mx  = fma2_(w2[t], Wx[s],  mx);
            my  = fma2_(w2[t], Wy[s],  my);
            exx = fma2_(w2[t], Wxx[s], exx);
            eyy = fma2_(w2[t], Wyy[s], eyy);
            exy = fma2_(w2[t], Wxy[s], exy);
        }

        u64 nmx = neg2_(mx);
        u64 sxx = fma2_(nmx, mx, exx);
        u64 syy = fma2_(neg2_(my), my, eyy);
        u64 sxy = fma2_(nmx, my, exy);

        u64 mxmy = mul2_(mx, my);
        u64 n1 = fma2_(two2, mxmy, c1_2);
        u64 n2 = fma2_(two2, sxy, c2_2);
        u64 num = mul2_(n1, n2);

        u64 myy = mul2_(my, my);
        u64 d1 = fma2_(mx, mx, myy);
        d1 = add2_(d1, c1_2);
        u64 d2 = add2_(add2_(sxx, syy), c2_2);
        u64 den = mul2_(d1, d2);

        float nlo, nhi, dlo, dhi;
        upk2(num, nlo, nhi);
        upk2(den, dlo, dhi);
        sum += __fdividef(nlo, dlo) + __fdividef(nhi, dhi);
    }
#undef HCONV

    // ---- block reduction ----
#pragma unroll
    for (int off = 16; off; off >>= 1)
        sum += __shfl_down_sync(0xffffffffu, sum, off);
    if ((tid & 31) == 0) wsum[tid >> 5] = sum;
    __syncthreads();

    // ---- last-block finalize (single-kernel) ----
    if (tid == 0) {
        float s = wsum[0] + wsum[1] + wsum[2] + wsum[3];
        atomicAdd(&g_acc, (double)s);
        __threadfence();
        unsigned t = atomicAdd(&g_tick, 1u);
        if (t == (unsigned)(nblocks - 1)) {
            double v = *(volatile double*)&g_acc;
            out[0] = (float)(v / ((double)BATCH * HH * WW));
            g_acc = 0.0;          // reset for next graph replay
            g_tick = 0;
            __threadfence();
        }
    }
}

extern "C" void kernel_launch(void* const* d_in, const int* in_sizes, int n_in,
                              void* d_out, int out_size)
{
    const float* x = (const float*)d_in[0];
    const float* y = (const float*)d_in[1];
    const float* k = (const float*)d_in[2];
    float* out = (float*)d_out;

    static int configured = 0;
    const int smem_bytes = 2 * TILE_H * SPITCH * (int)sizeof(float);
    if (!configured) {
        cudaFuncSetAttribute(ssim_main, cudaFuncAttributeMaxDynamicSharedMemorySize,
                             smem_bytes);
        configured = 1;
    }

    dim3 grid(WW / OUTW, HH / OUTH, BATCH);
    int nblocks = grid.x * grid.y * grid.z;
    ssim_main<<<grid, THREADS, smem_bytes>>>(x, y, k, out, nblocks);
}

// round 9
// speedup vs baseline: 1.0052x; 1.0052x over previous
#include <cuda_runtime.h>
#include <cuda_bf16.h>
#include <cstdint>

#define HH 512
#define WW 512
#define BATCH 32
#define THREADS 128
#define OUTW 256          // output cols per tile (2 per thread)
#define OUTH 8            // output rows per tile
#define SPITCH 264        // smem row pitch (floats): 4 left halo + 256 + 4 right
#define TILE_H (OUTH + 6) // 14
#define NCH 66            // 16-byte chunks per row per map (264 floats / 4)

typedef unsigned long long u64;

__device__ double g_acc = 0.0;
__device__ unsigned int g_tick = 0;

// ---- packed f32x2 helpers ----
static __device__ __forceinline__ u64 fma2_(u64 a, u64 b, u64 c) {
    u64 d; asm("fma.rn.f32x2 %0,%1,%2,%3;" : "=l"(d) : "l"(a), "l"(b), "l"(c)); return d;
}
static __device__ __forceinline__ u64 mul2_(u64 a, u64 b) {
    u64 d; asm("mul.rn.f32x2 %0,%1,%2;" : "=l"(d) : "l"(a), "l"(b)); return d;
}
static __device__ __forceinline__ u64 add2_(u64 a, u64 b) {
    u64 d; asm("add.rn.f32x2 %0,%1,%2;" : "=l"(d) : "l"(a), "l"(b)); return d;
}
static __device__ __forceinline__ u64 pk2(float lo, float hi) {
    u64 r; asm("mov.b64 %0,{%1,%2};" : "=l"(r) : "f"(lo), "f"(hi)); return r;
}
static __device__ __forceinline__ void upk2(u64 v, float& lo, float& hi) {
    asm("mov.b64 {%0,%1},%2;" : "=f"(lo), "=f"(hi) : "l"(v));
}
static __device__ __forceinline__ u64 neg2_(u64 a) { return a ^ 0x8000000080000000ULL; }
// pair {hi(a), lo(b)} — register re-pairing only (no shifts)
static __device__ __forceinline__ u64 sh2_(u64 a, u64 b) {
    unsigned al, ah, bl, bh;
    asm("mov.b64 {%0,%1},%2;" : "=r"(al), "=r"(ah) : "l"(a));
    asm("mov.b64 {%0,%1},%2;" : "=r"(bl), "=r"(bh) : "l"(b));
    u64 r;
    asm("mov.b64 %0,{%1,%2};" : "=l"(r) : "r"(ah), "r"(bl));
    return r;
}

static __device__ __forceinline__ void cp16(unsigned saddr, const float* gaddr, int srcsz) {
    asm volatile("cp.async.cg.shared.global [%0], [%1], 16, %2;"
                 :: "r"(saddr), "l"(gaddr), "r"(srcsz));
}

__global__ __launch_bounds__(THREADS, 5) void ssim_main(const float* __restrict__ x,
                                                        const float* __restrict__ y,
                                                        const float* __restrict__ kern,
                                                        float* __restrict__ out,
                                                        int nblocks)
{
    extern __shared__ float smem_dyn[];
    float (*sx)[SPITCH] = (float (*)[SPITCH])smem_dyn;
    float (*sy)[SPITCH] = (float (*)[SPITCH])(smem_dyn + TILE_H * SPITCH);
    __shared__ float wsum[4];

    const int tid  = threadIdx.x;
    const int col0 = blockIdx.x * OUTW;
    const int row0 = blockIdx.y * OUTH;
    const long base = (long)blockIdx.z * (HH * WW);

    // separable 1-D weights: v_i = sqrt(k[i][i])
    u64 w2[7];
#pragma unroll
    for (int t = 0; t < 7; t++) {
        float wt = sqrtf(__ldg(kern + t * 7 + t));
        w2[t] = pk2(wt, wt);
    }

    // ---- stage x,y tile via cp.async 16B chunks (zfill out-of-range) ----
    // smem col s <-> global col (col0 - 4 + s); row r <-> global row (row0 - 3 + r).
    // Each item = one (row, chunk) position; thread copies BOTH x and y chunks.
    // Since col0 in {0,256}, each chunk is fully in-image or fully out (clean zfill).
    for (int i = tid; i < TILE_H * NCH; i += THREADS) {
        int r  = i / NCH;
        int j  = i - r * NCH;
        int gr = row0 - 3 + r;
        int gc = col0 - 4 + 4 * j;
        bool ok = (gr >= 0) && (gr < HH) && (gc >= 0) && (gc < WW);
        long gi = base + (long)gr * WW + gc;
        const float* srcx = ok ? (x + gi) : x;
        const float* srcy = ok ? (y + gi) : y;
        int sz = ok ? 16 : 0;
        cp16((unsigned)__cvta_generic_to_shared(sx[r] + 4 * j), srcx, sz);
        cp16((unsigned)__cvta_generic_to_shared(sy[r] + 4 * j), srcy, sz);
    }
    asm volatile("cp.async.commit_group;");
    asm volatile("cp.async.wait_group 0;");
    __syncthreads();

    const u64 two2 = pk2(2.f, 2.f);
    const u64 c1_2 = pk2(1e-4f, 1e-4f);
    const u64 c2_2 = pk2(9e-4f, 9e-4f);

    u64 Wx[7], Wy[7], Wxx[7], Wyy[7], Wxy[7];
    float sum = 0.f;

    // horizontal 7-tap conv of (x,y,xx,yy,xy); outputs packed pair for global
    // cols (col0+2tid, col0+2tid+1). Aligned LDS.64 at smem cols 2tid..2tid+9;
    // tap t (lo pixel) lives at smem col 2tid+1+t.
#define HCONV(r, s)                                                          \
    {                                                                        \
        const float* rx_ = &sx[(r)][2 * tid];                                \
        const float* ry_ = &sy[(r)][2 * tid];                                \
        u64 e0 = *(const u64*)(rx_ + 0), e1 = *(const u64*)(rx_ + 2);        \
        u64 e2 = *(const u64*)(rx_ + 4), e3 = *(const u64*)(rx_ + 6);        \
        u64 e4 = *(const u64*)(rx_ + 8);                                     \
        u64 f0 = *(const u64*)(ry_ + 0), f1 = *(const u64*)(ry_ + 2);        \
        u64 f2 = *(const u64*)(ry_ + 4), f3 = *(const u64*)(ry_ + 6);        \
        u64 f4 = *(const u64*)(ry_ + 8);                                     \
        u64 xp[7] = {sh2_(e0, e1), e1, sh2_(e1, e2), e2,                     \
                     sh2_(e2, e3), e3, sh2_(e3, e4)};                        \
        u64 yp[7] = {sh2_(f0, f1), f1, sh2_(f1, f2), f2,                     \
                     sh2_(f2, f3), f3, sh2_(f3, f4)};                        \
        u64 wx0 = mul2_(w2[0], xp[0]);                                       \
        u64 wy0 = mul2_(w2[0], yp[0]);                                       \
        u64 a_ = wx0, b_ = wy0;                                              \
        u64 cxx_ = mul2_(wx0, xp[0]);                                        \
        u64 cyy_ = mul2_(wy0, yp[0]);                                        \
        u64 cxy_ = mul2_(wx0, yp[0]);                                        \
        _Pragma("unroll")                                                    \
        for (int t = 1; t < 7; t++) {                                        \
            u64 wx = mul2_(w2[t], xp[t]);                                    \
            u64 wy = mul2_(w2[t], yp[t]);                                    \
            a_   = add2_(a_, wx);                                            \
            b_   = add2_(b_, wy);                                            \
            cxx_ = fma2_(wx, xp[t], cxx_);                                   \
            cyy_ = fma2_(wy, yp[t], cyy_);                                   \
            cxy_ = fma2_(wx, yp[t], cxy_);                                   \
        }                                                                    \
        Wx[(s)] = a_; Wy[(s)] = b_;                                          \
        Wxx[(s)] = cxx_; Wyy[(s)] = cyy_; Wxy[(s)] = cxy_;                   \
    }

#pragma unroll
    for (int r = 0; r < 6; r++) {
        HCONV(r, r);
    }

#pragma unroll
    for (int r = 6; r < TILE_H; r++) {
        HCONV(r, r % 7);

        u64 mx  = mul2_(w2[0], Wx[(r - 6) % 7]);
        u64 my  = mul2_(w2[0], Wy[(r - 6) % 7]);
        u64 exx = mul2_(w2[0], Wxx[(r - 6) % 7]);
        u64 eyy = mul2_(w2[0], Wyy[(r - 6) % 7]);
        u64 exy = mul2_(w2[0], Wxy[(r - 6) % 7]);
#pragma unroll
        for (int t = 1; t < 7; t++) {
            int s = (r - 6 + t) % 7;
            mx  = fma2_(w2[t], Wx[s],  mx);
            my  = fma2_(w2[t], Wy[s],  my);
            exx = fma2_(w2[t], Wxx[s], exx);
            eyy = fma2_(w2[t], Wyy[s], eyy);
            exy = fma2_(w2[t], Wxy[s], exy);
        }

        u64 nmx = neg2_(mx);
        u64 sxx = fma2_(nmx, mx, exx);
        u64 syy = fma2_(neg2_(my), my, eyy);
        u64 sxy = fma2_(nmx, my, exy);

        u64 mxmy = mul2_(mx, my);
        u64 n1 = fma2_(two2, mxmy, c1_2);
        u64 n2 = fma2_(two2, sxy, c2_2);
        u64 num = mul2_(n1, n2);

        u64 myy = mul2_(my, my);
        u64 d1 = fma2_(mx, mx, myy);
        d1 = add2_(d1, c1_2);
        u64 d2 = add2_(add2_(sxx, syy), c2_2);
        u64 den = mul2_(d1, d2);

        float nlo, nhi, dlo, dhi;
        upk2(num, nlo, nhi);
        upk2(den, dlo, dhi);
        sum += __fdividef(nlo, dlo) + __fdividef(nhi, dhi);
    }
#undef HCONV

    // ---- block reduction ----
#pragma unroll
    for (int off = 16; off; off >>= 1)
        sum += __shfl_down_sync(0xffffffffu, sum, off);
    if ((tid & 31) == 0) wsum[tid >> 5] = sum;
    __syncthreads();

    // ---- last-block finalize (single-kernel) ----
    if (tid == 0) {
        float s = wsum[0] + wsum[1] + wsum[2] + wsum[3];
        atomicAdd(&g_acc, (double)s);
        __threadfence();
        unsigned t = atomicAdd(&g_tick, 1u);
        if (t == (unsigned)(nblocks - 1)) {
            double v = *(volatile double*)&g_acc;
            out[0] = (float)(v / ((double)BATCH * HH * WW));
            g_acc = 0.0;          // reset for next graph replay
            g_tick = 0;
            __threadfence();
        }
    }
}

extern "C" void kernel_launch(void* const* d_in, const int* in_sizes, int n_in,
                              void* d_out, int out_size)
{
    const float* x = (const float*)d_in[0];
    const float* y = (const float*)d_in[1];
    const float* k = (const float*)d_in[2];
    float* out = (float*)d_out;

    static int configured = 0;
    const int smem_bytes = 2 * TILE_H * SPITCH * (int)sizeof(float);
    if (!configured) {
        cudaFuncSetAttribute(ssim_main, cudaFuncAttributeMaxDynamicSharedMemorySize,
                             smem_bytes);
        configured = 1;
    }

    dim3 grid(WW / OUTW, HH / OUTH, BATCH);
    int nblocks = grid.x * grid.y * grid.z;
    ssim_main<<<grid, THREADS, smem_bytes>>>(x, y, k, out, nblocks);
}

// round 10
// speedup vs baseline: 1.0058x; 1.0006x over previous
#include <cuda_runtime.h>
#include <cuda_bf16.h>
#include <cstdint>

#define HH 512
#define WW 512
#define BATCH 32
#define THREADS 128
#define OUTW 256          // output cols per tile (2 per thread)
#define OUTH 16           // output rows per tile
#define SPITCH 264        // smem row pitch (floats): 4 left halo + 256 + 4 right
#define TILE_H (OUTH + 6) // 22 rows streamed through the ring
#define NCHX 66           // 16-byte chunks per row per map
#define TOTCH (2 * NCHX)  // 132 chunks per row (x + y)

typedef unsigned long long u64;

__device__ double g_acc = 0.0;
__device__ unsigned int g_tick = 0;

// ---- packed f32x2 helpers ----
static __device__ __forceinline__ u64 fma2_(u64 a, u64 b, u64 c) {
    u64 d; asm("fma.rn.f32x2 %0,%1,%2,%3;" : "=l"(d) : "l"(a), "l"(b), "l"(c)); return d;
}
static __device__ __forceinline__ u64 mul2_(u64 a, u64 b) {
    u64 d; asm("mul.rn.f32x2 %0,%1,%2;" : "=l"(d) : "l"(a), "l"(b)); return d;
}
static __device__ __forceinline__ u64 add2_(u64 a, u64 b) {
    u64 d; asm("add.rn.f32x2 %0,%1,%2;" : "=l"(d) : "l"(a), "l"(b)); return d;
}
static __device__ __forceinline__ u64 pk2(float lo, float hi) {
    u64 r; asm("mov.b64 %0,{%1,%2};" : "=l"(r) : "f"(lo), "f"(hi)); return r;
}
static __device__ __forceinline__ void upk2(u64 v, float& lo, float& hi) {
    asm("mov.b64 {%0,%1},%2;" : "=f"(lo), "=f"(hi) : "l"(v));
}
static __device__ __forceinline__ u64 neg2_(u64 a) { return a ^ 0x8000000080000000ULL; }
// pair {hi(a), lo(b)} — register re-pairing only
static __device__ __forceinline__ u64 sh2_(u64 a, u64 b) {
    unsigned al, ah, bl, bh;
    asm("mov.b64 {%0,%1},%2;" : "=r"(al), "=r"(ah) : "l"(a));
    asm("mov.b64 {%0,%1},%2;" : "=r"(bl), "=r"(bh) : "l"(b));
    u64 r;
    asm("mov.b64 %0,{%1,%2};" : "=l"(r) : "r"(ah), "r"(bl));
    return r;
}

static __device__ __forceinline__ void cp16(unsigned saddr, const float* gaddr, int srcsz) {
    asm volatile("cp.async.cg.shared.global [%0], [%1], 16, %2;"
                 :: "r"(saddr), "l"(gaddr), "r"(srcsz));
}

__global__ __launch_bounds__(THREADS, 5) void ssim_main(const float* __restrict__ x,
                                                        const float* __restrict__ y,
                                                        const float* __restrict__ kern,
                                                        float* __restrict__ out,
                                                        int nblocks)
{
    // 8-slot ring of rows (only 7 live at once); 16.9 KB static smem
    __shared__ float sx[8][SPITCH];
    __shared__ float sy[8][SPITCH];
    __shared__ float wsum[4];

    const int tid  = threadIdx.x;
    const int col0 = blockIdx.x * OUTW;
    const int row0 = blockIdx.y * OUTH;
    const long base = (long)blockIdx.z * (HH * WW);

    // separable 1-D weights: v_i = sqrt(k[i][i])
    u64 w2[7];
#pragma unroll
    for (int t = 0; t < 7; t++) {
        float wt = sqrtf(__ldg(kern + t * 7 + t));
        w2[t] = pk2(wt, wt);
    }

    // issue cp.async for logical row r into ring slot r&7 (x and y chunks).
    // smem col s <-> global col (col0 - 4 + s); global row = row0 - 3 + r.
    // col0 in {0,256} => every 16B chunk fully in-image or fully out (clean zfill).
#define LOAD_ROW(r)                                                           \
    {                                                                         \
        int slot_ = (r) & 7;                                                  \
        int gr_   = row0 - 3 + (r);                                           \
        bool rok_ = (gr_ >= 0) && (gr_ < HH);                                 \
        long gro_ = base + (long)gr_ * WW;                                    \
        _Pragma("unroll")                                                     \
        for (int i = tid; i < TOTCH; i += THREADS) {                          \
            int m_ = (i >= NCHX);                                             \
            int j_ = i - (m_ ? NCHX : 0);                                     \
            int gc_ = col0 - 4 + 4 * j_;                                      \
            bool ok_ = rok_ && (gc_ >= 0) && (gc_ < WW);                      \
            const float* gp_ = m_ ? y : x;                                    \
            const float* src_ = ok_ ? (gp_ + gro_ + gc_) : gp_;               \
            float* dst_ = (m_ ? sy[slot_] : sx[slot_]) + 4 * j_;              \
            cp16((unsigned)__cvta_generic_to_shared(dst_), src_, ok_ ? 16 : 0); \
        }                                                                     \
    }

    // prologue: issue rows 0..6, one commit group per row (7 groups in flight)
#pragma unroll
    for (int r = 0; r < 7; r++) {
        LOAD_ROW(r);
        asm volatile("cp.async.commit_group;");
    }

    const u64 two2 = pk2(2.f, 2.f);
    const u64 c1_2 = pk2(1e-4f, 1e-4f);
    const u64 c2_2 = pk2(9e-4f, 9e-4f);

    u64 Wx[7], Wy[7], Wxx[7], Wyy[7], Wxy[7];
    float sum = 0.f;

    // horizontal 7-tap conv of (x,y,xx,yy,xy) on ring slot sl; packed pair for
    // global cols (col0+2tid, col0+2tid+1). Aligned LDS.64 at smem cols 2tid..2tid+9.
#define HCONV(sl, s)                                                         \
    {                                                                        \
        const float* rx_ = &sx[(sl)][2 * tid];                               \
        const float* ry_ = &sy[(sl)][2 * tid];                               \
        u64 e0 = *(const u64*)(rx_ + 0), e1 = *(const u64*)(rx_ + 2);        \
        u64 e2 = *(const u64*)(rx_ + 4), e3 = *(const u64*)(rx_ + 6);        \
        u64 e4 = *(const u64*)(rx_ + 8);                                     \
        u64 f0 = *(const u64*)(ry_ + 0), f1 = *(const u64*)(ry_ + 2);        \
        u64 f2 = *(const u64*)(ry_ + 4), f3 = *(const u64*)(ry_ + 6);        \
        u64 f4 = *(const u64*)(ry_ + 8);                                     \
        u64 xp[7] = {sh2_(e0, e1), e1, sh2_(e1, e2), e2,                     \
                     sh2_(e2, e3), e3, sh2_(e3, e4)};                        \
        u64 yp[7] = {sh2_(f0, f1), f1, sh2_(f1, f2), f2,                     \
                     sh2_(f2, f3), f3, sh2_(f3, f4)};                        \
        u64 wx0 = mul2_(w2[0], xp[0]);                                       \
        u64 wy0 = mul2_(w2[0], yp[0]);                                       \
        u64 a_ = wx0, b_ = wy0;                                              \
        u64 cxx_ = mul2_(wx0, xp[0]);                                        \
        u64 cyy_ = mul2_(wy0, yp[0]);                                        \
        u64 cxy_ = mul2_(wx0, yp[0]);                                        \
        _Pragma("unroll")                                                    \
        for (int t = 1; t < 7; t++) {                                        \
            u64 wx = mul2_(w2[t], xp[t]);                                    \
            u64 wy = mul2_(w2[t], yp[t]);                                    \
            a_   = add2_(a_, wx);                                            \
            b_   = add2_(b_, wy);                                            \
            cxx_ = fma2_(wx, xp[t], cxx_);                                   \
            cyy_ = fma2_(wy, yp[t], cyy_);                                   \
            cxy_ = fma2_(wx, yp[t], cxy_);                                   \
        }                                                                    \
        Wx[(s)] = a_; Wy[(s)] = b_;                                          \
        Wxx[(s)] = cxx_; Wyy[(s)] = cyy_; Wxy[(s)] = cxy_;                   \
    }

    // streamed row loop: at iter r, groups issued = r+7 (dummies keep it uniform),
    // wait_group 6 => row r complete; barrier => visible to all threads.
#pragma unroll
    for (int r = 0; r < TILE_H; r++) {
        asm volatile("cp.async.wait_group 6;");
        __syncthreads();

        // issue row r+7 into slot (r-1)&7 — safe: barrier ordered all reads of row r-1
        if (r + 7 < TILE_H) {
            LOAD_ROW(r + 7);
        }
        asm volatile("cp.async.commit_group;");   // dummy group when no loads

        HCONV(r & 7, r % 7);

        if (r >= 6) {
            u64 mx  = mul2_(w2[0], Wx[(r - 6) % 7]);
            u64 my  = mul2_(w2[0], Wy[(r - 6) % 7]);
            u64 exx = mul2_(w2[0], Wxx[(r - 6) % 7]);
            u64 eyy = mul2_(w2[0], Wyy[(r - 6) % 7]);
            u64 exy = mul2_(w2[0], Wxy[(r - 6) % 7]);
#pragma unroll
            for (int t = 1; t < 7; t++) {
                int s = (r - 6 + t) % 7;
                mx  = fma2_(w2[t], Wx[s],  mx);
                my  = fma2_(w2[t], Wy[s],  my);
                exx = fma2_(w2[t], Wxx[s], exx);
                eyy = fma2_(w2[t], Wyy[s], eyy);
                exy = fma2_(w2[t], Wxy[s], exy);
            }

            u64 nmx = neg2_(mx);
            u64 sxx = fma2_(nmx, mx, exx);
            u64 syy = fma2_(neg2_(my), my, eyy);
            u64 sxy = fma2_(nmx, my, exy);

            u64 mxmy = mul2_(mx, my);
            u64 n1 = fma2_(two2, mxmy, c1_2);
            u64 n2 = fma2_(two2, sxy, c2_2);
            u64 num = mul2_(n1, n2);

            u64 myy = mul2_(my, my);
            u64 d1 = fma2_(mx, mx, myy);
            d1 = add2_(d1, c1_2);
            u64 d2 = add2_(add2_(sxx, syy), c2_2);
            u64 den = mul2_(d1, d2);

            float nlo, nhi, dlo, dhi;
            upk2(num, nlo, nhi);
            upk2(den, dlo, dhi);
            sum += __fdividef(nlo, dlo) + __fdividef(nhi, dhi);
        }
    }
#undef HCONV
#undef LOAD_ROW

    // ---- block reduction ----
#pragma unroll
    for (int off = 16; off; off >>= 1)
        sum += __shfl_down_sync(0xffffffffu, sum, off);
    if ((tid & 31) == 0) wsum[tid >> 5] = sum;
    __syncthreads();

    // ---- last-block finalize (single-kernel) ----
    if (tid == 0) {
        float s = wsum[0] + wsum[1] + wsum[2] + wsum[3];
        atomicAdd(&g_acc, (double)s);
        __threadfence();
        unsigned t = atomicAdd(&g_tick, 1u);
        if (t == (unsigned)(nblocks - 1)) {
            double v = *(volatile double*)&g_acc;
            out[0] = (float)(v / ((double)BATCH * HH * WW));
            g_acc = 0.0;          // reset for next graph replay
            g_tick = 0;
            __threadfence();
        }
    }
}

extern "C" void kernel_launch(void* const* d_in, const int* in_sizes, int n_in,
                              void* d_out, int out_size)
{
    const float* x = (const float*)d_in[0];
    const float* y = (const float*)d_in[1];
    const float* k = (const float*)d_in[2];
    float* out = (float*)d_out;

    dim3 grid(WW / OUTW, HH / OUTH, BATCH);
    int nblocks = grid.x * grid.y * grid.z;
    ssim_main<<<grid, THREADS>>>(x, y, k, out, nblocks);
}

// round 11
// speedup vs baseline: 1.0123x; 1.0065x over previous
#include <cuda_runtime.h>
#include <cuda_bf16.h>
#include <cstdint>

#define HH 512
#define WW 512
#define BATCH 32
#define THREADS 128
#define OUTW 256          // output cols per tile (2 per thread)
#define OUTH 32           // output rows per tile
#define SPITCH 264        // smem row pitch (floats): 4 left halo + 256 + 4 right
#define NROWS 38          // hconv rows (OUTH + 6)
#define NGROUPS 10        // 4-row load groups (40 rows loaded; last 2 unused)
#define NCHX 66           // 16-byte chunks per row per map
#define TOTCH 132         // chunks per row (x + y)
#define GCH (4 * TOTCH)   // 528 chunks per 4-row group

typedef unsigned long long u64;

__device__ double g_acc = 0.0;
__device__ unsigned int g_tick = 0;

// ---- packed f32x2 helpers ----
static __device__ __forceinline__ u64 fma2_(u64 a, u64 b, u64 c) {
    u64 d; asm("fma.rn.f32x2 %0,%1,%2,%3;" : "=l"(d) : "l"(a), "l"(b), "l"(c)); return d;
}
static __device__ __forceinline__ u64 mul2_(u64 a, u64 b) {
    u64 d; asm("mul.rn.f32x2 %0,%1,%2;" : "=l"(d) : "l"(a), "l"(b)); return d;
}
static __device__ __forceinline__ u64 add2_(u64 a, u64 b) {
    u64 d; asm("add.rn.f32x2 %0,%1,%2;" : "=l"(d) : "l"(a), "l"(b)); return d;
}
static __device__ __forceinline__ u64 pk2(float lo, float hi) {
    u64 r; asm("mov.b64 %0,{%1,%2};" : "=l"(r) : "f"(lo), "f"(hi)); return r;
}
static __device__ __forceinline__ void upk2(u64 v, float& lo, float& hi) {
    asm("mov.b64 {%0,%1},%2;" : "=f"(lo), "=f"(hi) : "l"(v));
}
static __device__ __forceinline__ u64 neg2_(u64 a) { return a ^ 0x8000000080000000ULL; }
// pair {hi(a), lo(b)} — register re-pairing only
static __device__ __forceinline__ u64 sh2_(u64 a, u64 b) {
    unsigned al, ah, bl, bh;
    asm("mov.b64 {%0,%1},%2;" : "=r"(al), "=r"(ah) : "l"(a));
    asm("mov.b64 {%0,%1},%2;" : "=r"(bl), "=r"(bh) : "l"(b));
    u64 r;
    asm("mov.b64 %0,{%1,%2};" : "=l"(r) : "r"(ah), "r"(bl));
    return r;
}

static __device__ __forceinline__ void cp16(unsigned saddr, const float* gaddr, int srcsz) {
    asm volatile("cp.async.cg.shared.global [%0], [%1], 16, %2;"
                 :: "r"(saddr), "l"(gaddr), "r"(srcsz));
}

__global__ __launch_bounds__(THREADS, 5) void ssim_main(const float* __restrict__ xg,
                                                        const float* __restrict__ yg,
                                                        const float* __restrict__ kern,
                                                        float* __restrict__ out,
                                                        int nblocks)
{
    // 16-row ring (4 groups of 4 rows); row r lives in slot r mod 16.
    __shared__ float sx[16][SPITCH];
    __shared__ float sy[16][SPITCH];
    __shared__ float wsum[4];

    const int tid  = threadIdx.x;
    const int col0 = blockIdx.x * OUTW;
    const int row0 = blockIdx.y * OUTH;
    const long base = (long)blockIdx.z * (HH * WW);

    // separable 1-D weights: v_i = sqrt(k[i][i])
    u64 w2[7];
#pragma unroll
    for (int t = 0; t < 7; t++) {
        float wt = sqrtf(__ldg(kern + t * 7 + t));
        w2[t] = pk2(wt, wt);
    }

    // ---- per-thread staging descriptors (5 chunks/group; j=4 only for tid<16) ----
    // chunk k = tid + 128j of a group: row-in-group dr = k/132, map = x|y, col chunk.
    // smem col s <-> global col (col0 - 4 + s); global row of group g = row0-3+4g+dr.
    int rowb[5]; bool cok[5]; const float* gsrc[5]; unsigned sdst[5];
#pragma unroll
    for (int j = 0; j < 5; j++) {
        int k  = tid + 128 * j;
        int kk = (k < GCH) ? k : 0;
        int dr  = kk / TOTCH;
        int rem = kk - dr * TOTCH;
        int m   = rem >= NCHX;
        int cc  = rem - (m ? NCHX : 0);
        int gc  = col0 - 4 + 4 * cc;
        cok[j]  = (gc >= 0) && (gc < WW);
        rowb[j] = row0 - 3 + dr;
        const float* gp = m ? yg : xg;
        gsrc[j] = gp + base + (long)rowb[j] * WW + gc;   // dereferenced only when ok
        sdst[j] = (unsigned)__cvta_generic_to_shared((m ? sy[dr] : sx[dr]) + 4 * cc);
    }

    // issue 4-row group G into ring slots ((G&3)*4 .. +3), one commit group
#define LOAD_GROUP(G)                                                          \
    do {                                                                       \
        const unsigned sb_ = (unsigned)(((G) & 3) * 4) * (SPITCH * 4);         \
        _Pragma("unroll")                                                      \
        for (int j = 0; j < 5; j++) {                                          \
            if (j < 4 || tid < 16) {                                           \
                int gr_ = rowb[j] + 4 * (G);                                   \
                bool ok_ = cok[j] && ((unsigned)gr_ < HH);                     \
                const float* s_ = ok_ ? (gsrc[j] + 4 * (G) * WW) : xg;         \
                cp16(sdst[j] + sb_, s_, ok_ ? 16 : 0);                         \
            }                                                                  \
        }                                                                      \
        asm volatile("cp.async.commit_group;");                                \
    } while (0)

    // prologue: 3 groups in flight
    LOAD_GROUP(0);
    LOAD_GROUP(1);
    LOAD_GROUP(2);

    const u64 two2 = pk2(2.f, 2.f);
    const u64 c1_2 = pk2(1e-4f, 1e-4f);
    const u64 c2_2 = pk2(9e-4f, 9e-4f);

    u64 Wx[7], Wy[7], Wxx[7], Wyy[7], Wxy[7];
    float sum = 0.f;

    // horizontal 7-tap conv of (x,y,xx,yy,xy) on ring slot sl -> window slot s
#define HCONV(sl, s)                                                         \
    {                                                                        \
        const float* rx_ = &sx[(sl)][2 * tid];                               \
        const float* ry_ = &sy[(sl)][2 * tid];                               \
        u64 e0 = *(const u64*)(rx_ + 0), e1 = *(const u64*)(rx_ + 2);        \
        u64 e2 = *(const u64*)(rx_ + 4), e3 = *(const u64*)(rx_ + 6);        \
        u64 e4 = *(const u64*)(rx_ + 8);                                     \
        u64 f0 = *(const u64*)(ry_ + 0), f1 = *(const u64*)(ry_ + 2);        \
        u64 f2 = *(const u64*)(ry_ + 4), f3 = *(const u64*)(ry_ + 6);        \
        u64 f4 = *(const u64*)(ry_ + 8);                                     \
        u64 xp[7] = {sh2_(e0, e1), e1, sh2_(e1, e2), e2,                     \
                     sh2_(e2, e3), e3, sh2_(e3, e4)};                        \
        u64 yp[7] = {sh2_(f0, f1), f1, sh2_(f1, f2), f2,                     \
                     sh2_(f2, f3), f3, sh2_(f3, f4)};                        \
        u64 wx0 = mul2_(w2[0], xp[0]);                                       \
        u64 wy0 = mul2_(w2[0], yp[0]);                                       \
        u64 a_ = wx0, b_ = wy0;                                              \
        u64 cxx_ = mul2_(wx0, xp[0]);                                        \
        u64 cyy_ = mul2_(wy0, yp[0]);                                        \
        u64 cxy_ = mul2_(wx0, yp[0]);                                        \
        _Pragma("unroll")                                                    \
        for (int t = 1; t < 7; t++) {                                        \
            u64 wx = mul2_(w2[t], xp[t]);                                    \
            u64 wy = mul2_(w2[t], yp[t]);                                    \
            a_   = add2_(a_, wx);                                            \
            b_   = add2_(b_, wy);                                            \
            cxx_ = fma2_(wx, xp[t], cxx_);                                   \
            cyy_ = fma2_(wy, yp[t], cyy_);                                   \
            cxy_ = fma2_(wx, yp[t], cxy_);                                   \
        }                                                                    \
        Wx[(s)] = a_; Wy[(s)] = b_;                                          \
        Wxx[(s)] = cxx_; Wyy[(s)] = cyy_; Wxy[(s)] = cxy_;                   \
    }

    // main loop: at each 4-row group boundary, wait (all but 2 newest groups
    // done => group g resident), barrier for cross-thread visibility, then
    // prefetch g+3 (overwrites rows of g-1, all consumed before this barrier).
#pragma unroll
    for (int r = 0; r < NROWS; r++) {
        if ((r & 3) == 0) {
            const int g = r >> 2;
            asm volatile("cp.async.wait_group 2;");
            __syncthreads();
            if (g + 3 < NGROUPS) {
                LOAD_GROUP(g + 3);
            } else {
                asm volatile("cp.async.commit_group;");   // dummy, keeps count uniform
            }
        }

        HCONV((((r >> 2) & 3) * 4 + (r & 3)), (r % 7));

        if (r >= 6) {
            u64 mx  = mul2_(w2[0], Wx[(r - 6) % 7]);
            u64 my  = mul2_(w2[0], Wy[(r - 6) % 7]);
            u64 exx = mul2_(w2[0], Wxx[(r - 6) % 7]);
            u64 eyy = mul2_(w2[0], Wyy[(r - 6) % 7]);
            u64 exy = mul2_(w2[0], Wxy[(r - 6) % 7]);
#pragma unroll
            for (int t = 1; t < 7; t++) {
                int s = (r - 6 + t) % 7;
                mx  = fma2_(w2[t], Wx[s],  mx);
                my  = fma2_(w2[t], Wy[s],  my);
                exx = fma2_(w2[t], Wxx[s], exx);
                eyy = fma2_(w2[t], Wyy[s], eyy);
                exy = fma2_(w2[t], Wxy[s], exy);
            }

            u64 nmx = neg2_(mx);
            u64 sxx = fma2_(nmx, mx, exx);
            u64 syy = fma2_(neg2_(my), my, eyy);
            u64 sxy = fma2_(nmx, my, exy);

            u64 mxmy = mul2_(mx, my);
            u64 n1 = fma2_(two2, mxmy, c1_2);
            u64 n2 = fma2_(two2, sxy, c2_2);
            u64 num = mul2_(n1, n2);

            u64 myy = mul2_(my, my);
            u64 d1 = fma2_(mx, mx, myy);
            d1 = add2_(d1, c1_2);
            u64 d2 = add2_(add2_(sxx, syy), c2_2);
            u64 den = mul2_(d1, d2);

            float nlo, nhi, dlo, dhi;
            upk2(num, nlo, nhi);
            upk2(den, dlo, dhi);
            sum += __fdividef(nlo, dlo) + __fdividef(nhi, dhi);
        }
    }
#undef HCONV
#undef LOAD_GROUP

    // ---- block reduction ----
#pragma unroll
    for (int off = 16; off; off >>= 1)
        sum += __shfl_down_sync(0xffffffffu, sum, off);
    if ((tid & 31) == 0) wsum[tid >> 5] = sum;
    __syncthreads();

    // ---- last-block finalize (single-kernel) ----
    if (tid == 0) {
        float s = wsum[0] + wsum[1] + wsum[2] + wsum[3];
        atomicAdd(&g_acc, (double)s);
        __threadfence();
        unsigned t = atomicAdd(&g_tick, 1u);
        if (t == (unsigned)(nblocks - 1)) {
            double v = *(volatile double*)&g_acc;
            out[0] = (float)(v / ((double)BATCH * HH * WW));
            g_acc = 0.0;          // reset for next graph replay
            g_tick = 0;
            __threadfence();
        }
    }
}

extern "C" void kernel_launch(void* const* d_in, const int* in_sizes, int n_in,
                              void* d_out, int out_size)
{
    const float* x = (const float*)d_in[0];
    const float* y = (const float*)d_in[1];
    const float* k = (const float*)d_in[2];
    float* out = (float*)d_out;

    dim3 grid(WW / OUTW, HH / OUTH, BATCH);
    int nblocks = grid.x * grid.y * grid.z;
    ssim_main<<<grid, THREADS>>>(x, y, k, out, nblocks);
}

// round 13
// speedup vs baseline: 1.0143x; 1.0020x over previous
#include <cuda_runtime.h>
#include <cuda_bf16.h>
#include <cstdint>

#define HH 512
#define WW 512
#define BATCH 32
#define THREADS 128
#define OUTW 256          // output cols per tile (2 per thread)
#define OUTH 16           // output rows per tile
#define SPITCH 264        // smem row pitch (floats): 4 left halo + 256 + 4 right
#define TILE_H (OUTH + 6) // 22
#define NCHX 66           // 16-byte chunks per row per map

typedef unsigned long long u64;

__device__ double g_acc = 0.0;
__device__ unsigned int g_tick = 0;

// ---- packed f32x2 helpers ----
static __device__ __forceinline__ u64 fma2_(u64 a, u64 b, u64 c) {
    u64 d; asm("fma.rn.f32x2 %0,%1,%2,%3;" : "=l"(d) : "l"(a), "l"(b), "l"(c)); return d;
}
static __device__ __forceinline__ u64 mul2_(u64 a, u64 b) {
    u64 d; asm("mul.rn.f32x2 %0,%1,%2;" : "=l"(d) : "l"(a), "l"(b)); return d;
}
static __device__ __forceinline__ u64 add2_(u64 a, u64 b) {
    u64 d; asm("add.rn.f32x2 %0,%1,%2;" : "=l"(d) : "l"(a), "l"(b)); return d;
}
static __device__ __forceinline__ u64 pk2(float lo, float hi) {
    u64 r; asm("mov.b64 %0,{%1,%2};" : "=l"(r) : "f"(lo), "f"(hi)); return r;
}
static __device__ __forceinline__ void upk2(u64 v, float& lo, float& hi) {
    asm("mov.b64 {%0,%1},%2;" : "=f"(lo), "=f"(hi) : "l"(v));
}
static __device__ __forceinline__ u64 neg2_(u64 a) { return a ^ 0x8000000080000000ULL; }
// pair {hi(a), lo(b)} — register re-pairing only
static __device__ __forceinline__ u64 sh2_(u64 a, u64 b) {
    unsigned al, ah, bl, bh;
    asm("mov.b64 {%0,%1},%2;" : "=r"(al), "=r"(ah) : "l"(a));
    asm("mov.b64 {%0,%1},%2;" : "=r"(bl), "=r"(bh) : "l"(b));
    u64 r;
    asm("mov.b64 %0,{%1,%2};" : "=l"(r) : "r"(ah), "r"(bl));
    return r;
}
static __device__ __forceinline__ float rcpa_(float a) {
    float r; asm("rcp.approx.f32 %0,%1;" : "=f"(r) : "f"(a)); return r;
}

static __device__ __forceinline__ void cp16(unsigned saddr, const float* gaddr, int srcsz) {
    asm volatile("cp.async.cg.shared.global [%0], [%1], 16, %2;"
                 :: "r"(saddr), "l"(gaddr), "r"(srcsz));
}

__global__ __launch_bounds__(THREADS) void ssim_main(const float* __restrict__ xg,
                                                     const float* __restrict__ yg,
                                                     const float* __restrict__ kern,
                                                     float* __restrict__ out,
                                                     int nblocks)
{
    extern __shared__ float smem_dyn[];
    float (*sx)[SPITCH] = (float (*)[SPITCH])smem_dyn;
    float (*sy)[SPITCH] = (float (*)[SPITCH])(smem_dyn + TILE_H * SPITCH);
    __shared__ float wsum[4];

    const int tid  = threadIdx.x;
    const int col0 = blockIdx.x * OUTW;
    const int row0 = blockIdx.y * OUTH;
    const long base = (long)blockIdx.z * (HH * WW);

    // separable 1-D weights: v_i = sqrt(k[i][i])
    u64 w2[7];
#pragma unroll
    for (int t = 0; t < 7; t++) {
        float wt = sqrtf(__ldg(kern + t * 7 + t));
        w2[t] = pk2(wt, wt);
    }

    // ---- division-free staging descriptors ----
    // Row has 132 16B chunks: 66 for x, 66 for y. Thread tid owns chunk tid;
    // threads 0..3 also own chunk 128+tid (y map, col chunk 62+tid).
    // smem col s <-> global col (col0 - 4 + s); global row of tile row r = row0-3+r.
    const int  m0   = tid >= NCHX;                    // 0 = x map, 1 = y map
    const int  cc0  = tid - (m0 ? NCHX : 0);          // col chunk 0..65
    const int  gc0  = col0 - 4 + 4 * cc0;
    const bool ok0  = (gc0 >= 0) && (gc0 < WW);
    const float* gp0 = m0 ? yg : xg;
    const long goff0 = base + gc0;                    // + gr*WW per row
    const unsigned sd0 = (unsigned)__cvta_generic_to_shared(
        (m0 ? sy[0] : sx[0]) + 4 * cc0);

    const int  cc1  = 62 + tid;                       // only used when tid < 4
    const int  gc1  = col0 - 4 + 4 * cc1;
    const bool ok1  = (gc1 >= 0) && (gc1 < WW);       // col check (gc1=512 at col0=256,tid=3)
    const long goff1 = base + gc1;
    const unsigned sd1 = (unsigned)__cvta_generic_to_shared(sy[0] + 4 * cc1);

#pragma unroll
    for (int r = 0; r < TILE_H; r++) {
        const int gr = row0 - 3 + r;
        const bool rok = ((unsigned)gr < HH);
        const bool o0 = ok0 && rok;
        cp16(sd0 + r * (SPITCH * 4), o0 ? (gp0 + goff0 + (long)gr * WW) : xg,
             o0 ? 16 : 0);
        if (tid < 4) {
            const bool o1 = ok1 && rok;
            cp16(sd1 + r * (SPITCH * 4), o1 ? (yg + goff1 + (long)gr * WW) : xg,
                 o1 ? 16 : 0);
        }
    }
    asm volatile("cp.async.commit_group;");
    asm volatile("cp.async.wait_group 0;");
    __syncthreads();

    const u64 two2 = pk2(2.f, 2.f);
    const u64 c1_2 = pk2(1e-4f, 1e-4f);
    const u64 c2_2 = pk2(9e-4f, 9e-4f);

    u64 Wx[7], Wy[7], Wxx[7], Wyy[7], Wxy[7];
    float sum = 0.f;

    // horizontal 7-tap conv of (x,y,xx,yy,xy); packed pair for global cols
    // (col0+2tid, col0+2tid+1). Aligned LDS.64 at smem cols 2tid..2tid+9.
#define HCONV(r, s)                                                          \
    {                                                                        \
        const float* rx_ = &sx[(r)][2 * tid];                                \
        const float* ry_ = &sy[(r)][2 * tid];                                \
        u64 e0 = *(const u64*)(rx_ + 0), e1 = *(const u64*)(rx_ + 2);        \
        u64 e2 = *(const u64*)(rx_ + 4), e3 = *(const u64*)(rx_ + 6);        \
        u64 e4 = *(const u64*)(rx_ + 8);                                     \
        u64 f0 = *(const u64*)(ry_ + 0), f1 = *(const u64*)(ry_ + 2);        \
        u64 f2 = *(const u64*)(ry_ + 4), f3 = *(const u64*)(ry_ + 6);        \
        u64 f4 = *(const u64*)(ry_ + 8);                                     \
        u64 xp[7] = {sh2_(e0, e1), e1, sh2_(e1, e2), e2,                     \
                     sh2_(e2, e3), e3, sh2_(e3, e4)};                        \
        u64 yp[7] = {sh2_(f0, f1), f1, sh2_(f1, f2), f2,                     \
                     sh2_(f2, f3), f3, sh2_(f3, f4)};                        \
        u64 wx0 = mul2_(w2[0], xp[0]);                                       \
        u64 wy0 = mul2_(w2[0], yp[0]);                                       \
        u64 a_ = wx0, b_ = wy0;                                              \
        u64 cxx_ = mul2_(wx0, xp[0]);                                        \
        u64 cyy_ = mul2_(wy0, yp[0]);                                        \
        u64 cxy_ = mul2_(wx0, yp[0]);                                        \
        _Pragma("unroll")                                                    \
        for (int t = 1; t < 7; t++) {                                        \
            u64 wx = mul2_(w2[t], xp[t]);                                    \
            u64 wy = mul2_(w2[t], yp[t]);                                    \
            a_   = add2_(a_, wx);                                            \
            b_   = add2_(b_, wy);                                            \
            cxx_ = fma2_(wx, xp[t], cxx_);                                   \
            cyy_ = fma2_(wy, yp[t], cyy_);                                   \
            cxy_ = fma2_(wx, yp[t], cxy_);                                   \
        }                                                                    \
        Wx[(s)] = a_; Wy[(s)] = b_;                                          \
        Wxx[(s)] = cxx_; Wyy[(s)] = cyy_; Wxy[(s)] = cxy_;                   \
    }

#pragma unroll
    for (int r = 0; r < 6; r++) {
        HCONV(r, r);
    }

#pragma unroll
    for (int r = 6; r < TILE_H; r++) {
        HCONV(r, r % 7);

        u64 mx  = mul2_(w2[0], Wx[(r - 6) % 7]);
        u64 my  = mul2_(w2[0], Wy[(r - 6) % 7]);
        u64 exx = mul2_(w2[0], Wxx[(r - 6) % 7]);
        u64 eyy = mul2_(w2[0], Wyy[(r - 6) % 7]);
        u64 exy = mul2_(w2[0], Wxy[(r - 6) % 7]);
#pragma unroll
        for (int t = 1; t < 7; t++) {
            int s = (r - 6 + t) % 7;
            mx  = fma2_(w2[t], Wx[s],  mx);
            my  = fma2_(w2[t], Wy[s],  my);
            exx = fma2_(w2[t], Wxx[s], exx);
            eyy = fma2_(w2[t], Wyy[s], eyy);
            exy = fma2_(w2[t], Wxy[s], exy);
        }

        u64 nmx = neg2_(mx);
        u64 sxx = fma2_(nmx, mx, exx);
        u64 syy = fma2_(neg2_(my), my, eyy);
        u64 sxy = fma2_(nmx, my, exy);

        u64 mxmy = mul2_(mx, my);
        u64 n1 = fma2_(two2, mxmy, c1_2);
        u64 n2 = fma2_(two2, sxy, c2_2);
        u64 num = mul2_(n1, n2);

        u64 myy = mul2_(my, my);
        u64 d1 = fma2_(mx, mx, myy);
        d1 = add2_(d1, c1_2);
        u64 d2 = add2_(add2_(sxx, syy), c2_2);
        u64 den = mul2_(d1, d2);

        // nlo/dlo + nhi/dhi = (nlo*dhi + nhi*dlo) * rcp(dlo*dhi) — one MUFU.RCP
        float nlo, nhi, dlo, dhi;
        upk2(num, nlo, nhi);
        upk2(den, dlo, dhi);
        float dd = dlo * dhi;
        float nn = fmaf(nlo, dhi, nhi * dlo);
        sum = fmaf(nn, rcpa_(dd), sum);
    }
#undef HCONV

    // ---- block reduction ----
#pragma unroll
    for (int off = 16; off; off >>= 1)
        sum += __shfl_down_sync(0xffffffffu, sum, off);
    if ((tid & 31) == 0) wsum[tid >> 5] = sum;
    __syncthreads();

    // ---- last-block finalize (single-kernel) ----
    if (tid == 0) {
        float s = wsum[0] + wsum[1] + wsum[2] + wsum[3];
        atomicAdd(&g_acc, (double)s);
        __threadfence();
        unsigned t = atomicAdd(&g_tick, 1u);
        if (t == (unsigned)(nblocks - 1)) {
            double v = *(volatile double*)&g_acc;
            out[0] = (float)(v / ((double)BATCH * HH * WW));
            g_acc = 0.0;          // reset for next graph replay
            g_tick = 0;
            __threadfence();
        }
    }
}

extern "C" void kernel_launch(void* const* d_in, const int* in_sizes, int n_in,
                              void* d_out, int out_size)
{
    const float* x = (const float*)d_in[0];
    const float* y = (const float*)d_in[1];
    const float* k = (const float*)d_in[2];
    float* out = (float*)d_out;

    static int configured = 0;
    const int smem_bytes = 2 * TILE_H * SPITCH * (int)sizeof(float);
    if (!configured) {
        cudaFuncSetAttribute(ssim_main, cudaFuncAttributeMaxDynamicSharedMemorySize,
                             smem_bytes);
        configured = 1;
    }

    dim3 grid(WW / OUTW, HH / OUTH, BATCH);
    int nblocks = grid.x * grid.y * grid.z;
    ssim_main<<<grid, THREADS, smem_bytes>>>(x, y, k, out, nblocks);
}